// round 16
// baseline (speedup 1.0000x reference)
#include <cuda_runtime.h>

#define NN   100000
#define NE   1600000
#define FIN  128
#define HID  64
#define NCLS 40

// ---- scratch (device globals; ONLY referenced inside device code) ----
__device__ __align__(16) float g_h   [NN * HID];   // GEMM output, pre-scaled by dinv[row]
__device__ __align__(16) float g_out [NN * HID];   // aggregated output (width 64)
__device__ float g_dinv[NN];
__device__ int   g_cnt [NN];          // in-degree (excl self-loop)
__device__ int   g_cur [NN];          // fill cursors
__device__ int   g_off [NN + 1];      // CSR offsets
__device__ int   g_csr [NE];          // src only, grouped by dst
__device__ int   g_is64;              // edge-index dtype probe

__device__ __forceinline__ int edge_at(const void* eiv, int idx) {
    long long v = g_is64 ? ((const long long*)eiv)[idx] : (long long)((const int*)eiv)[idx];
    return (v < 0) ? 0 : (v >= NN ? NN - 1 : (int)v);
}

// ------------------------------------------------------------------
// prep: zero counters; block 0 also runs the edge-dtype probe.
// ------------------------------------------------------------------
__global__ void k_prep(const unsigned int* __restrict__ w) {
    int i = blockIdx.x * blockDim.x + threadIdx.x;
    if (i < NN) { g_cnt[i] = 0; g_cur[i] = 0; }
    if (blockIdx.x == 0) {
        __shared__ int nz;
        if (threadIdx.x == 0) nz = 0;
        __syncthreads();
        int found = 0;
        for (int k = 1 + threadIdx.x * 128; k < 2 * NE; k += 256 * 128)
            if (w[k] != 0u) found = 1;
        if (found) atomicOr(&nz, 1);
        __syncthreads();
        if (threadIdx.x == 0) g_is64 = (nz == 0) ? 1 : 0;
    }
}

__global__ void k_hist(const void* __restrict__ eiv) {
    int e = blockIdx.x * blockDim.x + threadIdx.x;
    if (e >= NE) return;
    atomicAdd(&g_cnt[edge_at(eiv, NE + e)], 1);
}

__global__ void k_dinv() {
    int i = blockIdx.x * blockDim.x + threadIdx.x;
    if (i < NN) g_dinv[i] = rsqrtf((float)(g_cnt[i] + 1));   // +1 self-loop
}

// ------------------------------------------------------------------
// scan: offsets from g_cnt (single block, chunked)  [profiled launch]
// ------------------------------------------------------------------
#define SCAN_T 1024
__global__ void k_scan() {
    int t = threadIdx.x;
    const int chunk = (NN + SCAN_T - 1) / SCAN_T;
    int start = t * chunk;
    int end = start + chunk; if (end > NN) end = NN;
    int s = 0;
    for (int i = start; i < end; i++) { int c = g_cnt[i]; g_off[i] = s; s += c; }
    __shared__ int sums[SCAN_T];
    sums[t] = s;
    __syncthreads();
    for (int o = 1; o < SCAN_T; o <<= 1) {
        int v = (t >= o) ? sums[t - o] : 0;
        __syncthreads();
        sums[t] += v;
        __syncthreads();
    }
    int base = (t == 0) ? 0 : sums[t - 1];
    for (int i = start; i < end; i++) g_off[i] += base;
    if (t == SCAN_T - 1) g_off[NN] = sums[SCAN_T - 1];
}

__global__ void k_fill(const void* __restrict__ eiv) {
    int e = blockIdx.x * blockDim.x + threadIdx.x;
    if (e >= NE) return;
    int s = edge_at(eiv, e);
    int d = edge_at(eiv, NE + e);
    int idx = g_off[d] + atomicAdd(&g_cur[d], 1);
    g_csr[idx] = s;
}

// ------------------------------------------------------------------
// GEMM: g_h[n,F] = dinv[n] * act(Xsrc[n,K]) @ W[K,F]
// RF=8 for F=64 layers: 2x LDS.128 per k-step, 32 FMAs -> fewer
// L1 wavefronts per FMA than RF=4.
// ------------------------------------------------------------------
template <int K, int F, int RF, int RM, bool HASB, bool FROMG>
__global__ void k_gemm(const float* __restrict__ X,
                       const float* __restrict__ W,
                       const float* __restrict__ bin) {
    constexpr int NF = F / RF;
    constexpr int MT = 256 / NF;
    constexpr int TM = MT * RM;

    const float4* __restrict__ X4 =
        FROMG ? (const float4*)g_out : (const float4*)X;

    __shared__ __align__(16) float Ws[K * F];
    __shared__ float Bs[K];

    int tid = threadIdx.x;
    for (int i = tid; i < K * F; i += 256) Ws[i] = W[i];
    if (HASB) for (int i = tid; i < K; i += 256) Bs[i] = bin[i];
    __syncthreads();

    int fth  = tid % NF;
    int mth  = tid / NF;
    int f0   = fth * RF;
    int row0 = blockIdx.x * TM + mth * RM;

    float acc[RM][RF];
#pragma unroll
    for (int m = 0; m < RM; m++)
#pragma unroll
        for (int j = 0; j < RF; j++) acc[m][j] = 0.f;

#pragma unroll
    for (int k4 = 0; k4 < K; k4 += 4) {
        float xr[RM][4];
#pragma unroll
        for (int m = 0; m < RM; m++) {
            int r = row0 + m;
            float4 v = (r < NN) ? X4[(r * K + k4) >> 2]
                                : make_float4(0.f, 0.f, 0.f, 0.f);
            if (HASB) {
                v.x = fmaxf(v.x + Bs[k4 + 0], 0.f);
                v.y = fmaxf(v.y + Bs[k4 + 1], 0.f);
                v.z = fmaxf(v.z + Bs[k4 + 2], 0.f);
                v.w = fmaxf(v.w + Bs[k4 + 3], 0.f);
            }
            xr[m][0] = v.x; xr[m][1] = v.y; xr[m][2] = v.z; xr[m][3] = v.w;
        }
#pragma unroll
        for (int kk = 0; kk < 4; kk++) {
            float wv[RF];
            if (RF % 4 == 0) {
#pragma unroll
                for (int q = 0; q < RF / 4; q++) {
                    float4 w4 = *reinterpret_cast<const float4*>(
                        &Ws[(k4 + kk) * F + f0 + q * 4]);
                    wv[q * 4 + 0] = w4.x; wv[q * 4 + 1] = w4.y;
                    wv[q * 4 + 2] = w4.z; wv[q * 4 + 3] = w4.w;
                }
            } else {
#pragma unroll
                for (int j = 0; j < RF; j++) wv[j] = Ws[(k4 + kk) * F + f0 + j];
            }
#pragma unroll
            for (int j = 0; j < RF; j++) {
#pragma unroll
                for (int m = 0; m < RM; m++)
                    acc[m][j] = fmaf(xr[m][kk], wv[j], acc[m][j]);
            }
        }
    }

#pragma unroll
    for (int m = 0; m < RM; m++) {
        int r = row0 + m;
        if (r < NN) {
            float di = g_dinv[r];
#pragma unroll
            for (int j = 0; j < RF; j++)
                g_h[r * F + f0 + j] = acc[m][j] * di;
        }
    }
}

// ------------------------------------------------------------------
// Aggregation F=64: TWO warps per dst node (each half the edge list,
// 8-deep batches, lane-uniform csr loads), combined via smem.
// 256 thr/block = 4 nodes; grid 25000 exactly (no ragged sync).
// out[dst] = dinv[dst] * (h'[dst] + sum h'[src])
// ------------------------------------------------------------------
__global__ void k_agg64() {
    int tid  = threadIdx.x;
    int lane = tid & 31;
    int half = (tid >> 5) & 1;
    int nloc = tid >> 6;                         // node within block, 0..3
    int node = blockIdx.x * 4 + nloc;

    const float2* __restrict__ h2 = (const float2*)g_h;   // row = 32 float2

    int b = g_off[node], e = g_off[node + 1];
    int c0 = (e - b + 1) >> 1;
    int s0i = half ? (b + c0) : b;
    int s1i = half ? e : (b + c0);

    float2 a = half ? make_float2(0.f, 0.f) : h2[node * 32 + lane];  // self term

    int i = s0i;
    for (; i + 8 <= s1i; i += 8) {
        int s0 = g_csr[i    ], s1 = g_csr[i + 1];
        int s2 = g_csr[i + 2], s3 = g_csr[i + 3];
        int s4 = g_csr[i + 4], s5 = g_csr[i + 5];
        int s6 = g_csr[i + 6], s7 = g_csr[i + 7];
        float2 r0 = h2[s0 * 32 + lane];
        float2 r1 = h2[s1 * 32 + lane];
        float2 r2 = h2[s2 * 32 + lane];
        float2 r3 = h2[s3 * 32 + lane];
        float2 r4 = h2[s4 * 32 + lane];
        float2 r5 = h2[s5 * 32 + lane];
        float2 r6 = h2[s6 * 32 + lane];
        float2 r7 = h2[s7 * 32 + lane];
        a.x += (r0.x + r1.x) + (r2.x + r3.x) + (r4.x + r5.x) + (r6.x + r7.x);
        a.y += (r0.y + r1.y) + (r2.y + r3.y) + (r4.y + r5.y) + (r6.y + r7.y);
    }
    for (; i < s1i; i++) {
        float2 r = h2[g_csr[i] * 32 + lane];
        a.x += r.x; a.y += r.y;
    }

    __shared__ float2 red[4][32];
    if (half == 1) red[nloc][lane] = a;
    __syncthreads();
    if (half == 0) {
        float2 o = red[nloc][lane];
        float di = g_dinv[node];
        a.x = (a.x + o.x) * di;
        a.y = (a.y + o.y) * di;
        ((float2*)g_out)[node * 32 + lane] = a;
    }
}

// ------------------------------------------------------------------
// Layer-3 aggregation (F=40, 20 float2 lanes), TWO warps per node,
// fused with bias+relu+log_softmax (computed in warp 0).
// ------------------------------------------------------------------
__global__ void k_agg40_lsm(const float* __restrict__ b3, float* __restrict__ out) {
    int tid  = threadIdx.x;
    int lane = tid & 31;
    int half = (tid >> 5) & 1;
    int nloc = tid >> 6;
    int node = blockIdx.x * 4 + nloc;

    const float2* __restrict__ h2 = (const float2*)g_h;   // row = 20 float2
    bool act = lane < 20;
    int  sl  = act ? lane : 0;

    int b = g_off[node], e = g_off[node + 1];
    int c0 = (e - b + 1) >> 1;
    int s0i = half ? (b + c0) : b;
    int s1i = half ? e : (b + c0);

    float2 a = (half == 0 && act) ? h2[node * 20 + sl] : make_float2(0.f, 0.f);

    int i = s0i;
    for (; i + 8 <= s1i; i += 8) {
        int s0 = g_csr[i    ], s1 = g_csr[i + 1];
        int s2 = g_csr[i + 2], s3 = g_csr[i + 3];
        int s4 = g_csr[i + 4], s5 = g_csr[i + 5];
        int s6 = g_csr[i + 6], s7 = g_csr[i + 7];
        if (act) {
            float2 r0 = h2[s0 * 20 + sl];
            float2 r1 = h2[s1 * 20 + sl];
            float2 r2 = h2[s2 * 20 + sl];
            float2 r3 = h2[s3 * 20 + sl];
            float2 r4 = h2[s4 * 20 + sl];
            float2 r5 = h2[s5 * 20 + sl];
            float2 r6 = h2[s6 * 20 + sl];
            float2 r7 = h2[s7 * 20 + sl];
            a.x += (r0.x + r1.x) + (r2.x + r3.x) + (r4.x + r5.x) + (r6.x + r7.x);
            a.y += (r0.y + r1.y) + (r2.y + r3.y) + (r4.y + r5.y) + (r6.y + r7.y);
        }
    }
    for (; i < s1i; i++) {
        if (act) {
            float2 r = h2[g_csr[i] * 20 + sl];
            a.x += r.x; a.y += r.y;
        }
    }

    __shared__ float2 red[4][20];
    if (half == 1 && act) red[nloc][sl] = a;
    __syncthreads();
    if (half != 0) return;

    if (act) {
        float2 o = red[nloc][sl];
        a.x += o.x; a.y += o.y;
    }

    // dinv scale + bias + relu (two classes per active lane)
    float v0 = -1e30f, v1 = -1e30f;
    if (act) {
        float di = g_dinv[node];
        float2 bb = ((const float2*)b3)[sl];
        v0 = fmaxf(a.x * di + bb.x, 0.f);
        v1 = fmaxf(a.y * di + bb.y, 0.f);
    }

    // log_softmax over 40 values spread across 20 lanes x 2 (warp 0)
    float m = fmaxf(v0, v1);
#pragma unroll
    for (int o = 16; o > 0; o >>= 1)
        m = fmaxf(m, __shfl_xor_sync(0xFFFFFFFFu, m, o));

    float s = act ? (__expf(v0 - m) + __expf(v1 - m)) : 0.f;
#pragma unroll
    for (int o = 16; o > 0; o >>= 1)
        s += __shfl_xor_sync(0xFFFFFFFFu, s, o);

    float lse = m + __logf(s);
    if (act) {
        float2 r = make_float2(v0 - lse, v1 - lse);
        ((float2*)out)[node * 20 + sl] = r;
    }
}

extern "C" void kernel_launch(void* const* d_in, const int* in_sizes, int n_in,
                              void* d_out, int out_size) {
    // ---- bind inputs BY ELEMENT COUNT (robust to metadata ordering) ----
    const float* x  = 0;
    const void*  ei = 0;
    const float *W1 = 0, *W2 = 0, *W3 = 0, *b1 = 0, *b2 = 0, *b3 = 0;
    for (int i = 0; i < n_in; i++) {
        long long sz = in_sizes[i];
        const void* p = d_in[i];
        if      (sz == (long long)NN * FIN)  x  = (const float*)p;
        else if (sz == 2LL * NE)             ei = p;
        else if (sz == FIN * HID)            W1 = (const float*)p;
        else if (sz == HID * HID)            W2 = (const float*)p;
        else if (sz == HID * NCLS)           W3 = (const float*)p;
        else if (sz == NCLS)                 b3 = (const float*)p;
        else if (sz == HID) {
            if (!b1) b1 = (const float*)p; else b2 = (const float*)p;
        }
    }
    float* out = (float*)d_out;
    if (!x || !ei || !W1 || !W2 || !W3 || !b1 || !b2 || !b3) return;

    const int TB = 256;
    int gN = (NN + TB - 1) / TB;
    int gE = (NE + TB - 1) / TB;
    int gA = NN / 4;                    // 2-warp-per-node agg grids (exact)

    // 0: zero + dtype probe
    k_prep<<<gN, TB>>>((const unsigned int*)ei);
    // 1: degree histogram
    k_hist<<<gE, TB>>>(ei);
    // 2: dinv
    k_dinv<<<gN, TB>>>();
    // 3: offsets scan        [profiled launch]
    k_scan<<<1, SCAN_T>>>();
    // 4: CSR fill
    k_fill<<<gE, TB>>>(ei);
    // 5: layer-1 GEMM (128->64), RF=8
    k_gemm<FIN, HID, 8, 4, false, false><<<(NN + 127) / 128, TB>>>(x, W1, b3);
    // 6: layer-1 aggregation
    k_agg64<<<gA, TB>>>();
    // 7: layer-2 GEMM (64->64, relu(prev+b1) fused), RF=8
    k_gemm<HID, HID, 8, 4, true, true><<<(NN + 127) / 128, TB>>>(x, W2, b1);
    // 8: layer-2 aggregation
    k_agg64<<<gA, TB>>>();
    // 9: layer-3 GEMM (64->40, relu(prev+b2) fused)
    k_gemm<HID, NCLS, 5, 4, true, true><<<(NN + 127) / 128, TB>>>(x, W3, b2);
    // 10: layer-3 aggregation + bias + relu + log_softmax
    k_agg40_lsm<<<gA, TB>>>(b3, out);
}

// round 17
// speedup vs baseline: 1.7899x; 1.7899x over previous
#include <cuda_runtime.h>

#define NN   100000
#define NE   1600000
#define FIN  128
#define HID  64
#define NCLS 40

// ---- scratch (device globals; ONLY referenced inside device code) ----
__device__ __align__(16) float g_h   [NN * HID];   // GEMM output, pre-scaled by dinv[row]
__device__ __align__(16) float g_out [NN * HID];   // aggregated output (width 64)
__device__ float g_dinv[NN];
__device__ int   g_cnt [NN];          // in-degree (excl self-loop)
__device__ int   g_cur [NN];          // fill cursors
__device__ int   g_off [NN + 1];      // CSR offsets
__device__ int   g_csr [NE];          // src only, grouped by dst
__device__ int   g_is64;              // edge-index dtype probe

#define SCB 98                        // scan blocks: ceil(NN / 1024)
__device__ int   g_bsum[SCB];         // per-block count totals

__device__ __forceinline__ int edge_at(const void* eiv, int idx) {
    long long v = g_is64 ? ((const long long*)eiv)[idx] : (long long)((const int*)eiv)[idx];
    return (v < 0) ? 0 : (v >= NN ? NN - 1 : (int)v);
}

// ------------------------------------------------------------------
// prep: zero counters; block 0 also runs the edge-dtype probe.
// ------------------------------------------------------------------
__global__ void k_prep(const unsigned int* __restrict__ w) {
    int i = blockIdx.x * blockDim.x + threadIdx.x;
    if (i < NN) { g_cnt[i] = 0; g_cur[i] = 0; }
    if (blockIdx.x == 0) {
        __shared__ int nz;
        if (threadIdx.x == 0) nz = 0;
        __syncthreads();
        int found = 0;
        for (int k = 1 + threadIdx.x * 128; k < 2 * NE; k += 256 * 128)
            if (w[k] != 0u) found = 1;
        if (found) atomicOr(&nz, 1);
        __syncthreads();
        if (threadIdx.x == 0) g_is64 = (nz == 0) ? 1 : 0;
    }
}

__global__ void k_hist(const void* __restrict__ eiv) {
    int e = blockIdx.x * blockDim.x + threadIdx.x;
    if (e >= NE) return;
    atomicAdd(&g_cnt[edge_at(eiv, NE + e)], 1);
}

// ------------------------------------------------------------------
// Parallel scan phase A: 98 blocks x 256 thr, 4 counts per thread.
// Writes local-exclusive offsets, per-block total, and dinv (fused).
// ------------------------------------------------------------------
__global__ void k_scanA() {
    int t = threadIdx.x;
    int base = blockIdx.x * 1024 + t * 4;

    int c[4];
    int s = 0;
#pragma unroll
    for (int j = 0; j < 4; j++) {
        int idx = base + j;
        c[j] = (idx < NN) ? g_cnt[idx] : 0;
        s += c[j];
        if (idx < NN) g_dinv[idx] = rsqrtf((float)(c[j] + 1));
    }

    __shared__ int sh[256];
    sh[t] = s;
    __syncthreads();
#pragma unroll
    for (int o = 1; o < 256; o <<= 1) {
        int v = (t >= o) ? sh[t - o] : 0;
        __syncthreads();
        sh[t] += v;
        __syncthreads();
    }
    int run = (t == 0) ? 0 : sh[t - 1];
#pragma unroll
    for (int j = 0; j < 4; j++) {
        int idx = base + j;
        if (idx < NN) g_off[idx] = run;
        run += c[j];
    }
    if (t == 255) g_bsum[blockIdx.x] = sh[255];
}

// ------------------------------------------------------------------
// Parallel scan phase C: every block redundantly scans the 98 block
// sums in smem (cheap), then adds its base to its 1024 offsets.
// ------------------------------------------------------------------
__global__ void k_scanC() {
    int t = threadIdx.x;
    __shared__ int sh[128];
    if (t < 128) sh[t] = (t < SCB) ? g_bsum[t] : 0;
    __syncthreads();
#pragma unroll
    for (int o = 1; o < 128; o <<= 1) {
        int v = (t < 128 && t >= o) ? sh[t - o] : 0;
        __syncthreads();
        if (t < 128) sh[t] += v;
        __syncthreads();
    }
    int base = (blockIdx.x == 0) ? 0 : sh[blockIdx.x - 1];
    int idx0 = blockIdx.x * 1024 + t * 4;
#pragma unroll
    for (int j = 0; j < 4; j++) {
        int idx = idx0 + j;
        if (idx < NN) g_off[idx] += base;
    }
    if (blockIdx.x == 0 && t == 0) g_off[NN] = NE;
}

__global__ void k_fill(const void* __restrict__ eiv) {
    int e = blockIdx.x * blockDim.x + threadIdx.x;
    if (e >= NE) return;
    int s = edge_at(eiv, e);
    int d = edge_at(eiv, NE + e);
    int idx = g_off[d] + atomicAdd(&g_cur[d], 1);
    g_csr[idx] = s;
}

// ------------------------------------------------------------------
// GEMM: g_h[n,F] = dinv[n] * act(Xsrc[n,K]) @ W[K,F]
// (round-13 measured-best config: RF=4/5, RM=4, float4 X loads)
// ------------------------------------------------------------------
template <int K, int F, int RF, int RM, bool HASB, bool FROMG>
__global__ void k_gemm(const float* __restrict__ X,
                       const float* __restrict__ W,
                       const float* __restrict__ bin) {
    constexpr int NF = F / RF;
    constexpr int MT = 256 / NF;
    constexpr int TM = MT * RM;

    const float4* __restrict__ X4 =
        FROMG ? (const float4*)g_out : (const float4*)X;

    __shared__ __align__(16) float Ws[K * F];
    __shared__ float Bs[K];

    int tid = threadIdx.x;
    for (int i = tid; i < K * F; i += 256) Ws[i] = W[i];
    if (HASB) for (int i = tid; i < K; i += 256) Bs[i] = bin[i];
    __syncthreads();

    int fth  = tid % NF;
    int mth  = tid / NF;
    int f0   = fth * RF;
    int row0 = blockIdx.x * TM + mth * RM;

    float acc[RM][RF];
#pragma unroll
    for (int m = 0; m < RM; m++)
#pragma unroll
        for (int j = 0; j < RF; j++) acc[m][j] = 0.f;

#pragma unroll
    for (int k4 = 0; k4 < K; k4 += 4) {
        float xr[RM][4];
#pragma unroll
        for (int m = 0; m < RM; m++) {
            int r = row0 + m;
            float4 v = (r < NN) ? X4[(r * K + k4) >> 2]
                                : make_float4(0.f, 0.f, 0.f, 0.f);
            if (HASB) {
                v.x = fmaxf(v.x + Bs[k4 + 0], 0.f);
                v.y = fmaxf(v.y + Bs[k4 + 1], 0.f);
                v.z = fmaxf(v.z + Bs[k4 + 2], 0.f);
                v.w = fmaxf(v.w + Bs[k4 + 3], 0.f);
            }
            xr[m][0] = v.x; xr[m][1] = v.y; xr[m][2] = v.z; xr[m][3] = v.w;
        }
#pragma unroll
        for (int kk = 0; kk < 4; kk++) {
#pragma unroll
            for (int j = 0; j < RF; j++) {
                float wv = Ws[(k4 + kk) * F + f0 + j];
#pragma unroll
                for (int m = 0; m < RM; m++)
                    acc[m][j] = fmaf(xr[m][kk], wv, acc[m][j]);
            }
        }
    }

#pragma unroll
    for (int m = 0; m < RM; m++) {
        int r = row0 + m;
        if (r < NN) {
            float di = g_dinv[r];
#pragma unroll
            for (int j = 0; j < RF; j++)
                g_h[r * F + f0 + j] = acc[m][j] * di;
        }
    }
}

// ------------------------------------------------------------------
// Aggregation F=64: warp per dst node, all 32 lanes on one row
// (float2), lane-uniform csr loads (HW broadcast), 8-deep batches.
// out[dst] = dinv[dst] * (h'[dst] + sum h'[src])
// ------------------------------------------------------------------
__global__ void k_agg64() {
    int gw   = (blockIdx.x * blockDim.x + threadIdx.x) >> 5;
    int lane = threadIdx.x & 31;
    if (gw >= NN) return;

    const float2* __restrict__ h2 = (const float2*)g_h;   // row = 32 float2

    float2 a = h2[gw * 32 + lane];    // self term (h' has dinv folded)

    int b = g_off[gw], e = g_off[gw + 1];
    int i = b;
    for (; i + 8 <= e; i += 8) {
        int s0 = g_csr[i    ], s1 = g_csr[i + 1];
        int s2 = g_csr[i + 2], s3 = g_csr[i + 3];
        int s4 = g_csr[i + 4], s5 = g_csr[i + 5];
        int s6 = g_csr[i + 6], s7 = g_csr[i + 7];
        float2 r0 = h2[s0 * 32 + lane];
        float2 r1 = h2[s1 * 32 + lane];
        float2 r2 = h2[s2 * 32 + lane];
        float2 r3 = h2[s3 * 32 + lane];
        float2 r4 = h2[s4 * 32 + lane];
        float2 r5 = h2[s5 * 32 + lane];
        float2 r6 = h2[s6 * 32 + lane];
        float2 r7 = h2[s7 * 32 + lane];
        a.x += (r0.x + r1.x) + (r2.x + r3.x) + (r4.x + r5.x) + (r6.x + r7.x);
        a.y += (r0.y + r1.y) + (r2.y + r3.y) + (r4.y + r5.y) + (r6.y + r7.y);
    }
    for (; i < e; i++) {
        float2 r = h2[g_csr[i] * 32 + lane];
        a.x += r.x; a.y += r.y;
    }

    float di = g_dinv[gw];
    a.x *= di; a.y *= di;
    ((float2*)g_out)[gw * 32 + lane] = a;
}

// ------------------------------------------------------------------
// Layer-3 aggregation (F=40, 20 float2 lanes) fused with
// bias+relu+log_softmax. Writes final output directly.
// ------------------------------------------------------------------
__global__ void k_agg40_lsm(const float* __restrict__ b3, float* __restrict__ out) {
    int gw   = (blockIdx.x * blockDim.x + threadIdx.x) >> 5;
    int lane = threadIdx.x & 31;
    if (gw >= NN) return;

    const float2* __restrict__ h2 = (const float2*)g_h;   // row = 20 float2
    bool act = lane < 20;
    int  sl  = act ? lane : 0;

    float2 a = act ? h2[gw * 20 + sl] : make_float2(0.f, 0.f);

    int b = g_off[gw], e = g_off[gw + 1];
    int i = b;
    for (; i + 8 <= e; i += 8) {
        int s0 = g_csr[i    ], s1 = g_csr[i + 1];
        int s2 = g_csr[i + 2], s3 = g_csr[i + 3];
        int s4 = g_csr[i + 4], s5 = g_csr[i + 5];
        int s6 = g_csr[i + 6], s7 = g_csr[i + 7];
        if (act) {
            float2 r0 = h2[s0 * 20 + sl];
            float2 r1 = h2[s1 * 20 + sl];
            float2 r2 = h2[s2 * 20 + sl];
            float2 r3 = h2[s3 * 20 + sl];
            float2 r4 = h2[s4 * 20 + sl];
            float2 r5 = h2[s5 * 20 + sl];
            float2 r6 = h2[s6 * 20 + sl];
            float2 r7 = h2[s7 * 20 + sl];
            a.x += (r0.x + r1.x) + (r2.x + r3.x) + (r4.x + r5.x) + (r6.x + r7.x);
            a.y += (r0.y + r1.y) + (r2.y + r3.y) + (r4.y + r5.y) + (r6.y + r7.y);
        }
    }
    for (; i < e; i++) {
        if (act) {
            float2 r = h2[g_csr[i] * 20 + sl];
            a.x += r.x; a.y += r.y;
        }
    }

    // dinv scale + bias + relu (two classes per active lane)
    float v0 = -1e30f, v1 = -1e30f;
    if (act) {
        float di = g_dinv[gw];
        float2 bb = ((const float2*)b3)[sl];
        v0 = fmaxf(a.x * di + bb.x, 0.f);
        v1 = fmaxf(a.y * di + bb.y, 0.f);
    }

    // log_softmax over 40 values spread across 20 lanes x 2
    float m = fmaxf(v0, v1);
#pragma unroll
    for (int o = 16; o > 0; o >>= 1)
        m = fmaxf(m, __shfl_xor_sync(0xFFFFFFFFu, m, o));

    float s = act ? (__expf(v0 - m) + __expf(v1 - m)) : 0.f;
#pragma unroll
    for (int o = 16; o > 0; o >>= 1)
        s += __shfl_xor_sync(0xFFFFFFFFu, s, o);

    float lse = m + __logf(s);
    if (act) {
        float2 r = make_float2(v0 - lse, v1 - lse);
        ((float2*)out)[gw * 20 + sl] = r;
    }
}

extern "C" void kernel_launch(void* const* d_in, const int* in_sizes, int n_in,
                              void* d_out, int out_size) {
    // ---- bind inputs BY ELEMENT COUNT (robust to metadata ordering) ----
    const float* x  = 0;
    const void*  ei = 0;
    const float *W1 = 0, *W2 = 0, *W3 = 0, *b1 = 0, *b2 = 0, *b3 = 0;
    for (int i = 0; i < n_in; i++) {
        long long sz = in_sizes[i];
        const void* p = d_in[i];
        if      (sz == (long long)NN * FIN)  x  = (const float*)p;
        else if (sz == 2LL * NE)             ei = p;
        else if (sz == FIN * HID)            W1 = (const float*)p;
        else if (sz == HID * HID)            W2 = (const float*)p;
        else if (sz == HID * NCLS)           W3 = (const float*)p;
        else if (sz == NCLS)                 b3 = (const float*)p;
        else if (sz == HID) {
            if (!b1) b1 = (const float*)p; else b2 = (const float*)p;
        }
    }
    float* out = (float*)d_out;
    if (!x || !ei || !W1 || !W2 || !W3 || !b1 || !b2 || !b3) return;

    const int TB = 256;
    int gN = (NN + TB - 1) / TB;
    int gE = (NE + TB - 1) / TB;
    int gW = (NN * 32 + TB - 1) / TB;   // warp-per-node grids

    // 0: zero + dtype probe
    k_prep<<<gN, TB>>>((const unsigned int*)ei);
    // 1: degree histogram
    k_hist<<<gE, TB>>>(ei);
    // 2: scan phase A (local offsets + block sums + dinv)
    k_scanA<<<SCB, TB>>>();
    // 3: scan phase C (add block bases)
    k_scanC<<<SCB, TB>>>();
    // 4: CSR fill
    k_fill<<<gE, TB>>>(ei);
    // 5: layer-1 GEMM (128 -> 64)
    k_gemm<FIN, HID, 4, 4, false, false><<<(NN + 63) / 64, TB>>>(x, W1, b3);
    // 6: layer-1 aggregation
    k_agg64<<<gW, TB>>>();
    // 7: layer-2 GEMM (64 -> 64, relu(prev+b1) fused)
    k_gemm<HID, HID, 4, 4, true, true><<<(NN + 63) / 64, TB>>>(x, W2, b1);
    // 8: layer-2 aggregation
    k_agg64<<<gW, TB>>>();
    // 9: layer-3 GEMM (64 -> 40, relu(prev+b2) fused)
    k_gemm<HID, NCLS, 5, 4, true, true><<<(NN + 127) / 128, TB>>>(x, W3, b2);
    // 10: layer-3 aggregation + bias + relu + log_softmax
    k_agg40_lsm<<<gW, TB>>>(b3, out);
}